// round 1
// baseline (speedup 1.0000x reference)
#include <cuda_runtime.h>
#include <math.h>
#include <stdint.h>

// Problem constants
#define EN   65536      // edges
#define NN   200000     // nodes
#define MD   128        // MEM_DIM
#define TD   100        // TIME_DIM
#define EDIM 128        // EDGE_DIM
#define MSG  256        // MSG_DIM
#define KIN  484        // 2*MD + TD + EDIM
#define KX   512        // KIN padded to mult of 16
#define XR   131072     // 2*EN message rows
#define GD   384        // 3*MD gate dim

// ---------------------------------------------------------------------------
// Scratch (static device allocation; no cudaMalloc anywhere)
// ---------------------------------------------------------------------------
__device__ float g_X[(size_t)XR * KX];      // built message inputs  (268 MB)
__device__ float g_msum[(size_t)XR * MSG];  // per-updated-node msg sums (134 MB)
__device__ float g_gi[(size_t)XR * GD];     // gi = agg @ W_ih^T + b_ih (201 MB)
__device__ float g_gh[(size_t)XR * GD];     // gh = mem @ W_hh^T + b_hh (201 MB)
__device__ float g_Wpad[MSG * KX];          // W_msg zero-padded to K=512
__device__ int   g_counts[NN];
__device__ int   g_maxts[NN];               // float bits, ts >= 0 so int max works
__device__ int   g_slot[NN];                // node -> compact slot (valid iff count>0)
__device__ int   g_nodeof[XR];              // compact slot -> node
__device__ int   g_rowslot[XR];             // message row -> compact slot
__device__ float g_invcnt[XR];              // per-slot 1/count
__device__ int   g_U;                       // number of updated nodes

// ---------------------------------------------------------------------------
// Small utility kernels
// ---------------------------------------------------------------------------
__global__ void zero_f4(float4* p, int n4) {
    int i = blockIdx.x * blockDim.x + threadIdx.x;
    int stride = gridDim.x * blockDim.x;
    float4 z = make_float4(0.f, 0.f, 0.f, 0.f);
    for (; i < n4; i += stride) p[i] = z;
}

__global__ void copy_f4(float4* dstp, const float4* srcp, int n4) {
    int i = blockIdx.x * blockDim.x + threadIdx.x;
    int stride = gridDim.x * blockDim.x;
    for (; i < n4; i += stride) dstp[i] = srcp[i];
}

__global__ void init_nodes() {
    int i = blockIdx.x * blockDim.x + threadIdx.x;
    if (i < NN) { g_counts[i] = 0; g_maxts[i] = 0; }
    if (i == 0) g_U = 0;
}

__global__ void pad_w(const float* __restrict__ W) {
    int i = blockIdx.x * blockDim.x + threadIdx.x;
    if (i >= MSG * KX) return;
    int r = i / KX, c = i - r * KX;
    g_Wpad[i] = (c < KIN) ? W[r * KIN + c] : 0.f;
}

// Count node occurrences and running max-ts (2E entries: [src..., dst...])
__global__ void count_k(const int* __restrict__ src, const int* __restrict__ dst,
                        const float* __restrict__ ts) {
    int i = blockIdx.x * blockDim.x + threadIdx.x;
    if (i >= XR) return;
    int e = i & (EN - 1);
    int node = (i < EN) ? src[i] : dst[e];
    atomicAdd(&g_counts[node], 1);
    atomicMax(&g_maxts[node], __float_as_int(ts[e]));
}

// Compact updated nodes; write new_last_update_ts for all nodes
__global__ void compact_k(const float* __restrict__ last, float* __restrict__ out_ts) {
    int v = blockIdx.x * blockDim.x + threadIdx.x;
    if (v >= NN) return;
    int c = g_counts[v];
    float mt = __int_as_float(g_maxts[v]);   // 0.0f if untouched
    out_ts[v] = fmaxf(last[v], mt);
    if (c > 0) {
        int s = atomicAdd(&g_U, 1);
        g_slot[v]   = s;
        g_nodeof[s] = v;
        g_invcnt[s] = 1.0f / (float)c;
    }
}

// Build X[2E x 512]: rows [0,E) = x_src -> src node, rows [E,2E) = x_dst -> dst node
__global__ void build_x(const int* __restrict__ src, const int* __restrict__ dst,
                        const float* __restrict__ ts, const float* __restrict__ ef,
                        const float* __restrict__ mem, const float* __restrict__ last,
                        const float* __restrict__ freq, const float* __restrict__ phase) {
    int r = blockIdx.x;
    int e = r & (EN - 1);
    int s = src[e], d = dst[e];
    int a, b, node;
    float tval = ts[e], dt;
    if (r < EN) { a = d; b = s; node = s; dt = tval - last[s]; }   // x_src
    else        { a = s; b = d; node = d; dt = tval - last[d]; }   // x_dst
    if (threadIdx.x == 0) g_rowslot[r] = g_slot[node];
    float* xr = g_X + (size_t)r * KX;
    for (int c = threadIdx.x; c < KX; c += 128) {
        float v;
        if (c < MD)            v = mem[(size_t)a * MD + c];
        else if (c < 2 * MD)   v = mem[(size_t)b * MD + (c - MD)];
        else if (c < 2 * MD + TD) {
            int t = c - 2 * MD;
            v = cosf(dt * freq[t] + phase[t]);
        }
        else if (c < KIN)      v = ef[(size_t)e * EDIM + (c - 2 * MD - TD)];
        else                   v = 0.f;
        xr[c] = v;
    }
}

// ---------------------------------------------------------------------------
// Tiled SGEMM: C[M x N] = A[M x K] @ B[N x K]^T  (both K-contiguous, "NT")
// BM=BN=128, BK=16, 256 threads, 8x8 microtile per thread.
// MODE 0: C[m][n] = acc*rowScale[m] + bias[n]            (plain store)
// MODE 1: atomicAdd(Cbase + rowSlot[m]*MSG + n, relu(acc + bias[n]))
// Dynamic M via Mptr (reads g_U); rowMap gathers A rows.
// ---------------------------------------------------------------------------
template <int MODE>
__global__ __launch_bounds__(256) void sgemm(
    const float* __restrict__ A, int lda, const int* __restrict__ rowMap,
    const float* __restrict__ B, int K,
    float* __restrict__ C, int ldc,
    const float* __restrict__ bias,
    const float* __restrict__ rowScale,
    const int* __restrict__ rowSlot,
    int Mfixed, const int* __restrict__ Mptr)
{
    int M = Mptr ? *Mptr : Mfixed;
    int m0 = blockIdx.x * 128;
    if (m0 >= M) return;
    int n0 = blockIdx.y * 128;

    __shared__ float As[16][128];
    __shared__ float Bs[16][128];

    int tid = threadIdx.x;
    int tx = tid & 15, ty = tid >> 4;

    float acc[8][8];
#pragma unroll
    for (int i = 0; i < 8; i++)
#pragma unroll
        for (int j = 0; j < 8; j++) acc[i][j] = 0.f;

    for (int k0 = 0; k0 < K; k0 += 16) {
        // Load A tile (128 rows x 16 k), zero-fill rows beyond M
#pragma unroll
        for (int v = tid; v < 512; v += 256) {
            int row = v >> 2;
            int kc  = (v & 3) << 2;
            int gm  = m0 + row;
            float4 val = make_float4(0.f, 0.f, 0.f, 0.f);
            if (gm < M) {
                int ar = rowMap ? rowMap[gm] : gm;
                val = *reinterpret_cast<const float4*>(A + (size_t)ar * lda + k0 + kc);
            }
            As[kc + 0][row] = val.x; As[kc + 1][row] = val.y;
            As[kc + 2][row] = val.z; As[kc + 3][row] = val.w;
        }
        // Load B tile (128 out-features x 16 k); N always a multiple of 128
#pragma unroll
        for (int v = tid; v < 512; v += 256) {
            int row = v >> 2;
            int kc  = (v & 3) << 2;
            float4 val = *reinterpret_cast<const float4*>(B + (size_t)(n0 + row) * K + k0 + kc);
            Bs[kc + 0][row] = val.x; Bs[kc + 1][row] = val.y;
            Bs[kc + 2][row] = val.z; Bs[kc + 3][row] = val.w;
        }
        __syncthreads();
#pragma unroll
        for (int k = 0; k < 16; k++) {
            float a[8], b[8];
            *reinterpret_cast<float4*>(&a[0]) = *reinterpret_cast<const float4*>(&As[k][ty * 4]);
            *reinterpret_cast<float4*>(&a[4]) = *reinterpret_cast<const float4*>(&As[k][64 + ty * 4]);
            *reinterpret_cast<float4*>(&b[0]) = *reinterpret_cast<const float4*>(&Bs[k][tx * 4]);
            *reinterpret_cast<float4*>(&b[4]) = *reinterpret_cast<const float4*>(&Bs[k][64 + tx * 4]);
#pragma unroll
            for (int i = 0; i < 8; i++)
#pragma unroll
                for (int j = 0; j < 8; j++)
                    acc[i][j] = fmaf(a[i], b[j], acc[i][j]);
        }
        __syncthreads();
    }

#pragma unroll
    for (int i = 0; i < 8; i++) {
        int rr = (i < 4) ? (ty * 4 + i) : (64 + ty * 4 + i - 4);
        int gm = m0 + rr;
        if (gm >= M) continue;
        if (MODE == 1) {
            int slot = rowSlot[gm];
            float* base = C + (size_t)slot * MSG;
#pragma unroll
            for (int j = 0; j < 8; j++) {
                int cc = (j < 4) ? (tx * 4 + j) : (64 + tx * 4 + j - 4);
                int gn = n0 + cc;
                float v = fmaxf(acc[i][j] + bias[gn], 0.f);
                atomicAdd(base + gn, v);
            }
        } else {
            float sc = rowScale ? rowScale[gm] : 1.0f;
#pragma unroll
            for (int j = 0; j < 8; j++) {
                int cc = (j < 4) ? (tx * 4 + j) : (64 + tx * 4 + j - 4);
                int gn = n0 + cc;
                C[(size_t)gm * ldc + gn] = acc[i][j] * sc + bias[gn];
            }
        }
    }
}

// ---------------------------------------------------------------------------
// GRU gate fusion over compacted updated nodes
// ---------------------------------------------------------------------------
__global__ void gates_k(float* __restrict__ out_mem, const float* __restrict__ mem) {
    int idx = blockIdx.x * blockDim.x + threadIdx.x;
    int U = g_U;
    if (idx >= U * MD) return;
    int u = idx >> 7;        // /128
    int j = idx & 127;
    int v = g_nodeof[u];
    const float* gi = g_gi + (size_t)u * GD;
    const float* gh = g_gh + (size_t)u * GD;
    float ir = gi[j],          hr = gh[j];
    float iz = gi[MD + j],     hz = gh[MD + j];
    float in_ = gi[2 * MD + j], hn = gh[2 * MD + j];
    float m = mem[(size_t)v * MD + j];
    float r = 1.f / (1.f + expf(-(ir + hr)));
    float z = 1.f / (1.f + expf(-(iz + hz)));
    float nn = tanhf(in_ + r * hn);
    out_mem[(size_t)v * MD + j] = (1.f - z) * nn + z * m;
}

// ---------------------------------------------------------------------------
// Launch
// ---------------------------------------------------------------------------
extern "C" void kernel_launch(void* const* d_in, const int* in_sizes, int n_in,
                              void* d_out, int out_size) {
    const int*   src   = (const int*)d_in[0];
    const int*   dst   = (const int*)d_in[1];
    const float* ts    = (const float*)d_in[2];
    const float* ef    = (const float*)d_in[3];
    const float* mem   = (const float*)d_in[4];
    const float* last  = (const float*)d_in[5];
    const float* freq  = (const float*)d_in[6];
    const float* phase = (const float*)d_in[7];
    const float* Wmsg  = (const float*)d_in[8];
    const float* bmsg  = (const float*)d_in[9];
    const float* Wih   = (const float*)d_in[10];
    const float* Whh   = (const float*)d_in[11];
    const float* bih   = (const float*)d_in[12];
    const float* bhh   = (const float*)d_in[13];

    float* out_mem = (float*)d_out;
    float* out_ts  = out_mem + (size_t)NN * MD;

    // Symbol addresses for kernels that take scratch as parameters
    void *pX, *pMsum, *pGi, *pGh, *pWpad, *pInv, *pNode, *pRslot, *pU;
    cudaGetSymbolAddress(&pX,     g_X);
    cudaGetSymbolAddress(&pMsum,  g_msum);
    cudaGetSymbolAddress(&pGi,    g_gi);
    cudaGetSymbolAddress(&pGh,    g_gh);
    cudaGetSymbolAddress(&pWpad,  g_Wpad);
    cudaGetSymbolAddress(&pInv,   g_invcnt);
    cudaGetSymbolAddress(&pNode,  g_nodeof);
    cudaGetSymbolAddress(&pRslot, g_rowslot);
    cudaGetSymbolAddress(&pU,     g_U);

    // 1) Per-launch state reset (replay determinism)
    zero_f4<<<4096, 256>>>((float4*)pMsum, (XR * MSG) / 4);
    init_nodes<<<(NN + 255) / 256, 256>>>();
    pad_w<<<(MSG * KX + 255) / 256, 256>>>(Wmsg);

    // 2) Default output = old memory (updated rows overwritten later)
    copy_f4<<<4096, 256>>>((float4*)out_mem, (const float4*)mem, (NN * MD) / 4);

    // 3) Counts + max-ts, then compaction (also writes out_ts)
    count_k<<<XR / 256, 256>>>(src, dst, ts);
    compact_k<<<(NN + 255) / 256, 256>>>(last, out_ts);

    // 4) Build message-input matrix X
    build_x<<<XR, 128>>>(src, dst, ts, ef, mem, last, freq, phase);

    // 5) Message GEMM with fused relu + scatter-add into compact msg sums
    sgemm<1><<<dim3(XR / 128, MSG / 128), 256>>>(
        (const float*)pX, KX, nullptr,
        (const float*)pWpad, KX,
        (float*)pMsum, MSG, bmsg, nullptr, (const int*)pRslot,
        XR, nullptr);

    // 6) gi = (msg_sum @ W_ih^T) * invcnt + b_ih   (dynamic M = U)
    sgemm<0><<<dim3(XR / 128, GD / 128), 256>>>(
        (const float*)pMsum, MSG, nullptr,
        Wih, MSG,
        (float*)pGi, GD, bih, (const float*)pInv, nullptr,
        0, (const int*)pU);

    // 7) gh = memory[node_of] @ W_hh^T + b_hh      (gathered A rows)
    sgemm<0><<<dim3(XR / 128, GD / 128), 256>>>(
        mem, MD, (const int*)pNode,
        Whh, MD,
        (float*)pGh, GD, bhh, nullptr, nullptr,
        0, (const int*)pU);

    // 8) GRU gates -> scatter new memory rows
    gates_k<<<(XR * MD) / 256, 256>>>(out_mem, mem);
}

// round 3
// speedup vs baseline: 2.0949x; 2.0949x over previous
#include <cuda_runtime.h>
#include <math.h>
#include <stdint.h>

// Problem constants
#define EN   65536      // edges
#define NN   200000     // nodes
#define MD   128        // MEM_DIM
#define TD   100        // TIME_DIM
#define EDIM 128        // EDGE_DIM
#define MSG  256        // MSG_DIM
#define KIN  484        // 2*MD + TD + EDIM
#define KX   512        // KIN padded
#define XR   131072     // 2*EN message rows
#define GD   384        // 3*MD gate dim
#define SMS  20         // smem row stride in floats (bank-conflict-free)

// ---------------------------------------------------------------------------
// Scratch (static device allocation; no cudaMalloc anywhere)
// ---------------------------------------------------------------------------
__device__ float g_X[(size_t)XR * KX];
__device__ float g_msum[(size_t)XR * MSG];
__device__ float g_gi[(size_t)XR * GD];
__device__ float g_gh[(size_t)XR * GD];
__device__ float g_Wpad[MSG * KX];
__device__ int   g_counts[NN];
__device__ int   g_maxts[NN];
__device__ int   g_slot[NN];
__device__ int   g_nodeof[XR];
__device__ int   g_rowslot[XR];
__device__ float g_invcnt[XR];
__device__ int   g_U;

// ---------------------------------------------------------------------------
// Small utility kernels
// ---------------------------------------------------------------------------
__global__ void zero_f4(float4* p, int n4) {
    int i = blockIdx.x * blockDim.x + threadIdx.x;
    int stride = gridDim.x * blockDim.x;
    float4 z = make_float4(0.f, 0.f, 0.f, 0.f);
    for (; i < n4; i += stride) p[i] = z;
}

__global__ void copy_f4(float4* dstp, const float4* srcp, int n4) {
    int i = blockIdx.x * blockDim.x + threadIdx.x;
    int stride = gridDim.x * blockDim.x;
    for (; i < n4; i += stride) dstp[i] = srcp[i];
}

__global__ void init_nodes() {
    int i = blockIdx.x * blockDim.x + threadIdx.x;
    if (i < NN) { g_counts[i] = 0; g_maxts[i] = 0; }
    if (i == 0) g_U = 0;
}

__global__ void pad_w(const float* __restrict__ W) {
    int i = blockIdx.x * blockDim.x + threadIdx.x;
    if (i >= MSG * KX) return;
    int r = i / KX, c = i - r * KX;
    g_Wpad[i] = (c < KIN) ? W[r * KIN + c] : 0.f;
}

__global__ void count_k(const int* __restrict__ src, const int* __restrict__ dst,
                        const float* __restrict__ ts) {
    int i = blockIdx.x * blockDim.x + threadIdx.x;
    if (i >= XR) return;
    int e = i & (EN - 1);
    int node = (i < EN) ? src[i] : dst[e];
    atomicAdd(&g_counts[node], 1);
    atomicMax(&g_maxts[node], __float_as_int(ts[e]));
}

__global__ void compact_k(const float* __restrict__ last, float* __restrict__ out_ts) {
    int v = blockIdx.x * blockDim.x + threadIdx.x;
    if (v >= NN) return;
    int c = g_counts[v];
    float mt = __int_as_float(g_maxts[v]);
    out_ts[v] = fmaxf(last[v], mt);
    if (c > 0) {
        int s = atomicAdd(&g_U, 1);
        g_slot[v]   = s;
        g_nodeof[s] = v;
        g_invcnt[s] = 1.0f / (float)c;
    }
}

// Build X[2E x 512]: rows [0,E)=x_src -> src node, rows [E,2E)=x_dst -> dst node
__global__ void build_x(const int* __restrict__ src, const int* __restrict__ dst,
                        const float* __restrict__ ts, const float* __restrict__ ef,
                        const float* __restrict__ mem, const float* __restrict__ last,
                        const float* __restrict__ freq, const float* __restrict__ phase) {
    int r = blockIdx.x;
    int e = r & (EN - 1);
    int s = src[e], d = dst[e];
    int a, b, node;
    float tval = ts[e], dt;
    if (r < EN) { a = d; b = s; node = s; dt = tval - last[s]; }   // x_src
    else        { a = s; b = d; node = d; dt = tval - last[d]; }   // x_dst
    if (threadIdx.x == 0) g_rowslot[r] = g_slot[node];
    float* xr = g_X + (size_t)r * KX;
    for (int c = threadIdx.x; c < KX; c += 128) {
        float v;
        if (c < MD)            v = mem[(size_t)a * MD + c];
        else if (c < 2 * MD)   v = mem[(size_t)b * MD + (c - MD)];
        else if (c < 2 * MD + TD) {
            int t = c - 2 * MD;
            v = cosf(dt * freq[t] + phase[t]);
        }
        else if (c < KIN)      v = ef[(size_t)e * EDIM + (c - 2 * MD - TD)];
        else                   v = 0.f;
        xr[c] = v;
    }
}

// ---------------------------------------------------------------------------
// mma.sync tf32 helpers
// ---------------------------------------------------------------------------
__device__ __forceinline__ unsigned smem_u32(const void* p) {
    return (unsigned)__cvta_generic_to_shared(p);
}
__device__ __forceinline__ void cp16(unsigned sa, const void* g, int sz) {
    asm volatile("cp.async.cg.shared.global [%0], [%1], 16, %2;\n"
                 :: "r"(sa), "l"(g), "r"(sz));
}
__device__ __forceinline__ uint32_t f2tf(float f) {
    uint32_t u;
    asm("cvt.rna.tf32.f32 %0, %1;\n" : "=r"(u) : "f"(f));
    return u;
}
__device__ __forceinline__ void mma8(float* c, const uint32_t* a, const uint32_t* b) {
    asm volatile(
        "mma.sync.aligned.m16n8k8.row.col.f32.tf32.tf32.f32 "
        "{%0,%1,%2,%3}, {%4,%5,%6,%7}, {%8,%9}, {%0,%1,%2,%3};\n"
        : "+f"(c[0]), "+f"(c[1]), "+f"(c[2]), "+f"(c[3])
        : "r"(a[0]), "r"(a[1]), "r"(a[2]), "r"(a[3]), "r"(b[0]), "r"(b[1]));
}

// ---------------------------------------------------------------------------
// TF32 tensor-core GEMM: C[MxN] = A[MxK] @ B[NxK]^T ("NT", both K-contig)
// 128x128x16 tiles, cp.async double buffer, 8 warps x (32x64) warp tiles.
// MODE 0: C[m][n] = acc*rowScale[m] + bias[n]
// MODE 1: atomicAdd(C + rowSlot[m]*ldc + n, relu(acc + bias[n]))
// ---------------------------------------------------------------------------
template <int MODE>
__global__ __launch_bounds__(256) void mma_gemm(
    const float* __restrict__ A, int lda, const int* __restrict__ rowMap,
    const float* __restrict__ B, int K,
    float* __restrict__ C, int ldc,
    const float* __restrict__ bias,
    const float* __restrict__ rowScale,
    const int* __restrict__ rowSlot,
    int Mfixed, const int* __restrict__ Mptr)
{
    __shared__ float As[2][128 * SMS];
    __shared__ float Bs[2][128 * SMS];

    int M = Mptr ? *Mptr : Mfixed;
    int m0 = blockIdx.x * 128;
    if (m0 >= M) return;
    int n0 = blockIdx.y * 128;

    int tid = threadIdx.x;
    unsigned sA = smem_u32(&As[0][0]);
    unsigned sB = smem_u32(&Bs[0][0]);

    auto stage = [&](int b, int k0) {
#pragma unroll
        for (int it = 0; it < 2; it++) {
            int ch = tid + it * 256;
            int row = ch >> 2, c4 = (ch & 3) << 2;
            int gm = m0 + row;
            const float* gp = A;
            int sz = 0;
            if (gm < M) {
                int ar = rowMap ? rowMap[gm] : gm;
                gp = A + (size_t)ar * lda + k0 + c4;
                sz = 16;
            }
            cp16(sA + (unsigned)((b * 128 * SMS) + row * SMS + c4) * 4u, gp, sz);
        }
#pragma unroll
        for (int it = 0; it < 2; it++) {
            int ch = tid + it * 256;
            int row = ch >> 2, c4 = (ch & 3) << 2;
            cp16(sB + (unsigned)((b * 128 * SMS) + row * SMS + c4) * 4u,
                 B + (size_t)(n0 + row) * K + k0 + c4, 16);
        }
    };

    int lane = tid & 31, g = lane >> 2, tg = lane & 3;
    int wid = tid >> 5;
    int wm = (wid & 3) * 32;   // warp M offset
    int wn = (wid >> 2) * 64;  // warp N offset

    float c[2][8][4];
#pragma unroll
    for (int mt = 0; mt < 2; mt++)
#pragma unroll
        for (int nt = 0; nt < 8; nt++)
#pragma unroll
            for (int q = 0; q < 4; q++) c[mt][nt][q] = 0.f;

    stage(0, 0);
    asm volatile("cp.async.commit_group;\n");
    int buf = 0;

    for (int k0 = 0; k0 < K; k0 += 16) {
        if (k0 + 16 < K) {
            stage(buf ^ 1, k0 + 16);
            asm volatile("cp.async.commit_group;\n");
            asm volatile("cp.async.wait_group 1;\n");
        } else {
            asm volatile("cp.async.wait_group 0;\n");
        }
        __syncthreads();

        const float* as = &As[buf][0];
        const float* bs = &Bs[buf][0];
#pragma unroll
        for (int ks = 0; ks < 16; ks += 8) {
            uint32_t af[2][4], bf[8][2];
#pragma unroll
            for (int mt = 0; mt < 2; mt++) {
                int r0 = wm + mt * 16 + g;
                af[mt][0] = f2tf(as[r0 * SMS + ks + tg]);
                af[mt][1] = f2tf(as[(r0 + 8) * SMS + ks + tg]);
                af[mt][2] = f2tf(as[r0 * SMS + ks + tg + 4]);
                af[mt][3] = f2tf(as[(r0 + 8) * SMS + ks + tg + 4]);
            }
#pragma unroll
            for (int nt = 0; nt < 8; nt++) {
                int n = wn + nt * 8 + g;
                bf[nt][0] = f2tf(bs[n * SMS + ks + tg]);
                bf[nt][1] = f2tf(bs[n * SMS + ks + tg + 4]);
            }
#pragma unroll
            for (int mt = 0; mt < 2; mt++)
#pragma unroll
                for (int nt = 0; nt < 8; nt++)
                    mma8(c[mt][nt], af[mt], bf[nt]);
        }
        __syncthreads();
        buf ^= 1;
    }

    // Epilogue
#pragma unroll
    for (int mt = 0; mt < 2; mt++) {
        int rA = m0 + wm + mt * 16 + g;
        int rB = rA + 8;
        if (MODE == 1) {
            int sa = rowSlot[rA], sb = rowSlot[rB];
            float* baseA = C + (size_t)sa * ldc;
            float* baseB = C + (size_t)sb * ldc;
#pragma unroll
            for (int nt = 0; nt < 8; nt++) {
                int col = n0 + wn + nt * 8 + 2 * tg;
                float b0v = bias[col], b1v = bias[col + 1];
                atomicAdd(baseA + col,     fmaxf(c[mt][nt][0] + b0v, 0.f));
                atomicAdd(baseA + col + 1, fmaxf(c[mt][nt][1] + b1v, 0.f));
                atomicAdd(baseB + col,     fmaxf(c[mt][nt][2] + b0v, 0.f));
                atomicAdd(baseB + col + 1, fmaxf(c[mt][nt][3] + b1v, 0.f));
            }
        } else {
            bool va = rA < M, vb = rB < M;
            float sAc = 1.f, sBc = 1.f;
            if (rowScale) {
                if (va) sAc = rowScale[rA];
                if (vb) sBc = rowScale[rB];
            }
#pragma unroll
            for (int nt = 0; nt < 8; nt++) {
                int col = n0 + wn + nt * 8 + 2 * tg;
                float b0v = bias[col], b1v = bias[col + 1];
                if (va) {
                    float2 v = make_float2(c[mt][nt][0] * sAc + b0v,
                                           c[mt][nt][1] * sAc + b1v);
                    *reinterpret_cast<float2*>(C + (size_t)rA * ldc + col) = v;
                }
                if (vb) {
                    float2 v = make_float2(c[mt][nt][2] * sBc + b0v,
                                           c[mt][nt][3] * sBc + b1v);
                    *reinterpret_cast<float2*>(C + (size_t)rB * ldc + col) = v;
                }
            }
        }
    }
}

// ---------------------------------------------------------------------------
// GRU gate fusion over compacted updated nodes
// ---------------------------------------------------------------------------
__global__ void gates_k(float* __restrict__ out_mem, const float* __restrict__ mem) {
    int idx = blockIdx.x * blockDim.x + threadIdx.x;
    int U = g_U;
    if (idx >= U * MD) return;
    int u = idx >> 7;
    int j = idx & 127;
    int v = g_nodeof[u];
    const float* gi = g_gi + (size_t)u * GD;
    const float* gh = g_gh + (size_t)u * GD;
    float ir = gi[j],           hr = gh[j];
    float iz = gi[MD + j],      hz = gh[MD + j];
    float in_ = gi[2 * MD + j], hn = gh[2 * MD + j];
    float m = mem[(size_t)v * MD + j];
    float r = 1.f / (1.f + expf(-(ir + hr)));
    float z = 1.f / (1.f + expf(-(iz + hz)));
    float nn = tanhf(in_ + r * hn);
    out_mem[(size_t)v * MD + j] = (1.f - z) * nn + z * m;
}

// ---------------------------------------------------------------------------
// Launch
// ---------------------------------------------------------------------------
extern "C" void kernel_launch(void* const* d_in, const int* in_sizes, int n_in,
                              void* d_out, int out_size) {
    const int*   src   = (const int*)d_in[0];
    const int*   dst   = (const int*)d_in[1];
    const float* ts    = (const float*)d_in[2];
    const float* ef    = (const float*)d_in[3];
    const float* mem   = (const float*)d_in[4];
    const float* last  = (const float*)d_in[5];
    const float* freq  = (const float*)d_in[6];
    const float* phase = (const float*)d_in[7];
    const float* Wmsg  = (const float*)d_in[8];
    const float* bmsg  = (const float*)d_in[9];
    const float* Wih   = (const float*)d_in[10];
    const float* Whh   = (const float*)d_in[11];
    const float* bih   = (const float*)d_in[12];
    const float* bhh   = (const float*)d_in[13];

    float* out_mem = (float*)d_out;
    float* out_ts  = out_mem + (size_t)NN * MD;

    void *pX, *pMsum, *pGi, *pGh, *pWpad, *pInv, *pNode, *pRslot, *pU;
    cudaGetSymbolAddress(&pX,     g_X);
    cudaGetSymbolAddress(&pMsum,  g_msum);
    cudaGetSymbolAddress(&pGi,    g_gi);
    cudaGetSymbolAddress(&pGh,    g_gh);
    cudaGetSymbolAddress(&pWpad,  g_Wpad);
    cudaGetSymbolAddress(&pInv,   g_invcnt);
    cudaGetSymbolAddress(&pNode,  g_nodeof);
    cudaGetSymbolAddress(&pRslot, g_rowslot);
    cudaGetSymbolAddress(&pU,     g_U);

    // 1) Per-launch state reset (replay determinism)
    zero_f4<<<4096, 256>>>((float4*)pMsum, (XR * MSG) / 4);
    init_nodes<<<(NN + 255) / 256, 256>>>();
    pad_w<<<(MSG * KX + 255) / 256, 256>>>(Wmsg);

    // 2) Default output = old memory
    copy_f4<<<4096, 256>>>((float4*)out_mem, (const float4*)mem, (NN * MD) / 4);

    // 3) Counts + max-ts, then compaction (writes out_ts)
    count_k<<<XR / 256, 256>>>(src, dst, ts);
    compact_k<<<(NN + 255) / 256, 256>>>(last, out_ts);

    // 4) Build message-input matrix X
    build_x<<<XR, 128>>>(src, dst, ts, ef, mem, last, freq, phase);

    // 5) Message GEMM: relu + scatter-add into compact msg sums (tensor cores)
    mma_gemm<1><<<dim3(XR / 128, MSG / 128), 256>>>(
        (const float*)pX, KX, nullptr,
        (const float*)pWpad, KX,
        (float*)pMsum, MSG, bmsg, nullptr, (const int*)pRslot,
        XR, nullptr);

    // 6) gi = (msg_sum @ W_ih^T) * invcnt + b_ih   (dynamic M = U)
    mma_gemm<0><<<dim3(XR / 128, GD / 128), 256>>>(
        (const float*)pMsum, MSG, nullptr,
        Wih, MSG,
        (float*)pGi, GD, bih, (const float*)pInv, nullptr,
        0, (const int*)pU);

    // 7) gh = memory[node_of] @ W_hh^T + b_hh      (gathered A rows)
    mma_gemm<0><<<dim3(XR / 128, GD / 128), 256>>>(
        mem, MD, (const int*)pNode,
        Whh, MD,
        (float*)pGh, GD, bhh, nullptr, nullptr,
        0, (const int*)pU);

    // 8) GRU gates -> scatter new memory rows
    gates_k<<<(XR * MD) / 256, 256>>>(out_mem, mem);
}